// round 10
// baseline (speedup 1.0000x reference)
#include <cuda_runtime.h>
#include <cuda_bf16.h>
#include <cstdint>

// SConv2dAvg as HMMA GEMM with cp.async-pipelined gather.
// D[o,n] = sum_k W[o,k] P[k,n]; per CTA n = 16 b x 16 px = 256 cols.
// K=576 in 18 chunks of 32 (k' = (r*3+s)*64 + c).
// 3-product double-bf16 split: Whi*Phi + Whi*Plo + Wlo*Phi.
// Gather: cp.async fp32 -> smem staging (thread-private slots), convert via LDS.
// 8 warps, warp tile m64 x n32. Operand rows 144B (16B-aligned, conflict-free).

#define Y_DIM   63
#define COUT    64
#define KTOT    576
#define THREADS 256

// smem bytes:
//   stage fp32: 2 x [32 c][256 rows] = 2 x 32768   @ 0
//   B bf16:     256 rows x 144B  (hi 0-63 | lo 64-127 | pad) @ 65536
//   A bf16:      64 rows x 144B  (hi | lo | pad)             @ 102400
#define B_OFF   65536
#define A_OFF   102400
#define SMEM_TOTAL 111616

__device__ unsigned short g_Ahi[COUT * KTOT];
__device__ unsigned short g_Alo[COUT * KTOT];

__global__ void prep_A_kernel(const float* __restrict__ w) {
    int idx = blockIdx.x * 256 + threadIdx.x;
    if (idx >= COUT * KTOT) return;
    int o  = idx / KTOT;
    int kp = idx - o * KTOT;        // k' = rs*64 + c
    int rs = kp >> 6;
    int c  = kp & 63;
    float v = w[o * KTOT + c * 9 + rs];
    unsigned short hi;
    asm("cvt.rn.bf16.f32 %0, %1;" : "=h"(hi) : "f"(v));
    float rem = v - __uint_as_float(((unsigned)hi) << 16);
    unsigned short lo;
    asm("cvt.rn.bf16.f32 %0, %1;" : "=h"(lo) : "f"(rem));
    g_Ahi[idx] = hi;
    g_Alo[idx] = lo;
}

__device__ __forceinline__ uint32_t pack_bf16x2(float x, float y) {
    uint32_t r;
    asm("cvt.rn.satfinite.bf16x2.f32 %0, %2, %1;" : "=r"(r) : "f"(x), "f"(y));
    return r;
}

#define MMA(acc, a, b)                                                         \
    asm volatile("mma.sync.aligned.m16n8k16.row.col.f32.bf16.bf16.f32 "        \
        "{%0,%1,%2,%3}, {%4,%5,%6,%7}, {%8,%9}, {%0,%1,%2,%3};"                \
        : "+f"((acc)[0]), "+f"((acc)[1]), "+f"((acc)[2]), "+f"((acc)[3])       \
        : "r"((a)[0]), "r"((a)[1]), "r"((a)[2]), "r"((a)[3]),                  \
          "r"((b)[0]), "r"((b)[1]))

// issue 32 x 4B cp.async for chunk i into stage buf (i&1); thread-private slots
#define ISSUE_CP(i) do {                                                       \
    int rs_ = (i) >> 1;                                                        \
    const float* src_ = pbase + (rs_ / 3) * 128 + (rs_ - (rs_ / 3) * 3)        \
                      + (((i) & 1) << 19);       /* +32 c = 32<<14 floats */   \
    uint32_t dst_ = sb + ((i) & 1) * 32768 + tid * 4;                          \
    _Pragma("unroll")                                                          \
    for (int c_ = 0; c_ < 32; c_++)                                            \
        asm volatile("cp.async.ca.shared.global [%0], [%1], 4;"                \
            :: "r"(dst_ + c_ * 1024), "l"(src_ + ((long)c_ << 14)) : "memory");\
    asm volatile("cp.async.commit_group;" ::: "memory");                       \
} while (0)

// load chunk i's A slab (64 rows x [hi 64B | lo 64B]) from L2 into regs aa[2]
#define LDA(i)                                                                 \
    _Pragma("unroll") for (int t_ = 0; t_ < 2; t_++) {                         \
        int idx_ = tid + t_ * 256;       /* 0..511 */                          \
        int m_ = idx_ >> 3, q_ = idx_ & 7;                                     \
        aa[t_] = *(const uint4*)((const char*)(q_ < 4 ? g_Ahi : g_Alo)         \
                                 + m_ * 1152 + (i) * 64 + (q_ & 3) * 16);      \
    }

#define STA()                                                                  \
    _Pragma("unroll") for (int t_ = 0; t_ < 2; t_++) {                         \
        int idx_ = tid + t_ * 256;                                             \
        int m_ = idx_ >> 3, q_ = idx_ & 7;                                     \
        *(uint4*)(smem + A_OFF + m_ * 144 + q_ * 16) = aa[t_];                 \
    }

// convert this thread's staged row (32 fp32) -> bf16 hi|lo operand row
#define CONVERT(p) do {                                                        \
    const float* st_ = (const float*)(smem + (p) * 32768) + tid;               \
    _Pragma("unroll") for (int j_ = 0; j_ < 4; j_++) {                         \
        float v_[8];                                                           \
        _Pragma("unroll") for (int c_ = 0; c_ < 8; c_++)                       \
            v_[c_] = st_[(j_ * 8 + c_) * 256];                                 \
        uint32_t hp_[4], lp_[4];                                               \
        _Pragma("unroll") for (int q_ = 0; q_ < 4; q_++) {                     \
            float a0_ = v_[2 * q_], a1_ = v_[2 * q_ + 1];                      \
            hp_[q_] = pack_bf16x2(a0_, a1_);                                   \
            float r0_ = a0_ - __uint_as_float(hp_[q_] << 16);                  \
            float r1_ = a1_ - __uint_as_float(hp_[q_] & 0xFFFF0000u);          \
            lp_[q_] = pack_bf16x2(r0_, r1_);                                   \
        }                                                                      \
        char* d_ = smem + B_OFF + tid * 144 + j_ * 16;                         \
        *(uint4*)d_        = make_uint4(hp_[0], hp_[1], hp_[2], hp_[3]);       \
        *(uint4*)(d_ + 64) = make_uint4(lp_[0], lp_[1], lp_[2], lp_[3]);       \
    }                                                                          \
} while (0)

// one k16 step (kq in {0,1}); scalar LDS fragments, 144B rows
#define COMPUTE_KQ(kq) do {                                                    \
    uint32_t bh_[4][2], bl_[4][2];                                             \
    _Pragma("unroll") for (int nf = 0; nf < 4; nf++) {                         \
        const char* pb = smem + B_OFF                                          \
                       + (w * 32 + nf * 8 + fr) * 144 + (kq) * 32 + fq * 4;    \
        bh_[nf][0] = *(const uint32_t*)pb;                                     \
        bh_[nf][1] = *(const uint32_t*)(pb + 16);                              \
        bl_[nf][0] = *(const uint32_t*)(pb + 64);                              \
        bl_[nf][1] = *(const uint32_t*)(pb + 64 + 16);                         \
    }                                                                          \
    _Pragma("unroll") for (int mf = 0; mf < 4; mf++) {                         \
        const char* pa = smem + A_OFF + (mf * 16 + fr) * 144 + (kq) * 32 + fq * 4; \
        uint32_t ah_[4], al_[4];                                               \
        ah_[0] = *(const uint32_t*)pa;                                         \
        ah_[1] = *(const uint32_t*)(pa + 8 * 144);                             \
        ah_[2] = *(const uint32_t*)(pa + 16);                                  \
        ah_[3] = *(const uint32_t*)(pa + 8 * 144 + 16);                        \
        al_[0] = *(const uint32_t*)(pa + 64);                                  \
        al_[1] = *(const uint32_t*)(pa + 64 + 8 * 144);                        \
        al_[2] = *(const uint32_t*)(pa + 64 + 16);                             \
        al_[3] = *(const uint32_t*)(pa + 64 + 8 * 144 + 16);                   \
        _Pragma("unroll") for (int nf = 0; nf < 4; nf++) {                     \
            MMA(acc[mf][nf], ah_, bh_[nf]);                                    \
            MMA(acc[mf][nf], ah_, bl_[nf]);                                    \
            MMA(acc[mf][nf], al_, bh_[nf]);                                    \
        }                                                                      \
    }                                                                          \
} while (0)

__global__ __launch_bounds__(THREADS, 2) void sconv_hmma_kernel(
    const float* __restrict__ input,
    const float* __restrict__ bias,
    const int*   __restrict__ selh,
    const int*   __restrict__ selw,
    float*       __restrict__ out)
{
    extern __shared__ char smem[];
    const uint32_t sb = (uint32_t)__cvta_generic_to_shared(smem);

    const int tid  = threadIdx.x;
    const int lane = tid & 31;
    const int w    = tid >> 5;
    const int fq   = lane & 3;
    const int fr   = lane >> 2;

    const int y   = blockIdx.x >> 2;
    const int px0 = (blockIdx.x & 3) * 16;

    // gather mapping: thread owns B row tid = b*16 + pxl
    const int b   = tid >> 4;
    const int pxl = tid & 15;
    const int pxc = min(px0 + pxl, Y_DIM - 1);
    const int sh  = selh[y * Y_DIM + pxc];
    const int sw  = selw[y * Y_DIM + pxc];
    const float* pbase = input + (b << 20) + (2 * y + sh) * 128 + 2 * pxc + sw;

    float acc[4][4][4];
#pragma unroll
    for (int i = 0; i < 4; i++)
#pragma unroll
        for (int j = 0; j < 4; j++)
#pragma unroll
            for (int q = 0; q < 4; q++) acc[i][j][q] = 0.f;

    ISSUE_CP(0);

    for (int ch = 0; ch < 18; ch++) {
        uint4 aa[2];
        if (ch < 17) ISSUE_CP(ch + 1);
        LDA(ch);                                   // L2 LDG, hidden under cp wait
        if (ch < 17)
            asm volatile("cp.async.wait_group 1;" ::: "memory");
        else
            asm volatile("cp.async.wait_group 0;" ::: "memory");
        CONVERT(ch & 1);                           // thread-private staging slot
        STA();
        __syncthreads();                           // operands ready for all warps
        COMPUTE_KQ(0);
        COMPUTE_KQ(1);
        __syncthreads();                           // compute done before next overwrite
    }

    // ---- epilogue: scalar stores (odd output strides) ----
    const int npx   = min(16, Y_DIM - px0);
    const int ybase = y * Y_DIM + px0;

#pragma unroll
    for (int mf = 0; mf < 4; mf++) {
        const int o = mf * 16 + fr;
        const float bo0 = __ldg(bias + o);
        const float bo8 = __ldg(bias + o + 8);
#pragma unroll
        for (int nf = 0; nf < 4; nf++) {
            int n    = w * 32 + nf * 8 + 2 * fq;
            int bcol = n >> 4;
            int pp   = n & 15;
            long base0 = ((long)(bcol * COUT + o)) * (Y_DIM * Y_DIM) + ybase + pp;
            long base8 = base0 + 8L * (Y_DIM * Y_DIM);
            if (pp < npx) {
                out[base0] = acc[mf][nf][0] + bo0;
                out[base8] = acc[mf][nf][2] + bo8;
            }
            if (pp + 1 < npx) {
                out[base0 + 1] = acc[mf][nf][1] + bo0;
                out[base8 + 1] = acc[mf][nf][3] + bo8;
            }
        }
    }
}

extern "C" void kernel_launch(void* const* d_in, const int* in_sizes, int n_in,
                              void* d_out, int out_size)
{
    const float* input  = (const float*)d_in[0];
    const float* weight = (const float*)d_in[1];
    const float* bias   = (const float*)d_in[2];
    const int*   selh   = (const int*)d_in[3];
    const int*   selw   = (const int*)d_in[4];
    float*       out    = (float*)d_out;

    cudaFuncSetAttribute(sconv_hmma_kernel,
                         cudaFuncAttributeMaxDynamicSharedMemorySize, SMEM_TOTAL);

    prep_A_kernel<<<(COUT * KTOT + 255) / 256, 256>>>(weight);
    sconv_hmma_kernel<<<Y_DIM * 4, THREADS, SMEM_TOTAL>>>(input, bias, selh, selw, out);
}

// round 11
// speedup vs baseline: 1.3261x; 1.3261x over previous
#include <cuda_runtime.h>
#include <cuda_bf16.h>
#include <cstdint>

// SConv2dAvg as GEMM on HMMA (mma.sync bf16, 3-product double-bf16 split).
// D[o,n] = sum_k W[o,k] P[k,n];  n = b*16+px tile of 256; k' = (r*3+s)*64 + c.
// R5 baseline + high-MLP pipelined gather (all chunk LDGs in flight before use).

#define Y_DIM   63
#define COUT    64
#define KTOT    576
#define THREADS 256

// smem bytes: Ahi[64][144] Alo[64][144] Bhi[256][144] Blo[256][144]
#define AHI_OFF 0
#define ALO_OFF 9216
#define BHI_OFF 18432
#define BLO_OFF 55296
#define SMEM_TOTAL 92160

__device__ unsigned short g_Ahi[COUT * KTOT];
__device__ unsigned short g_Alo[COUT * KTOT];

__global__ void prep_A_kernel(const float* __restrict__ w) {
    int idx = blockIdx.x * 256 + threadIdx.x;
    if (idx >= COUT * KTOT) return;
    int o  = idx / KTOT;
    int kp = idx - o * KTOT;        // k' = rs*64 + c
    int rs = kp >> 6;
    int c  = kp & 63;
    float v = w[o * KTOT + c * 9 + rs];
    unsigned short hi;
    asm("cvt.rn.bf16.f32 %0, %1;" : "=h"(hi) : "f"(v));
    float rem = v - __uint_as_float(((unsigned)hi) << 16);
    unsigned short lo;
    asm("cvt.rn.bf16.f32 %0, %1;" : "=h"(lo) : "f"(rem));
    g_Ahi[idx] = hi;
    g_Alo[idx] = lo;
}

__device__ __forceinline__ uint32_t pack_bf16x2(float x, float y) {
    uint32_t r;
    asm("cvt.rn.satfinite.bf16x2.f32 %0, %2, %1;" : "=r"(r) : "f"(x), "f"(y));
    return r;
}

#define MMA(acc, a, b)                                                         \
    asm volatile("mma.sync.aligned.m16n8k16.row.col.f32.bf16.bf16.f32 "        \
        "{%0,%1,%2,%3}, {%4,%5,%6,%7}, {%8,%9}, {%0,%1,%2,%3};"                \
        : "+f"((acc)[0]), "+f"((acc)[1]), "+f"((acc)[2]), "+f"((acc)[3])       \
        : "r"((a)[0]), "r"((a)[1]), "r"((a)[2]), "r"((a)[3]),                  \
          "r"((b)[0]), "r"((b)[1]))

// load round r (16 c-values) of this thread's B row
#define LDGV(v, r)                                                             \
    _Pragma("unroll") for (int j_ = 0; j_ < 16; j_++)                          \
        (v)[j_] = __ldg(p + ((((r) << 4) + j_) << 14));

// convert round r -> bf16 hi/lo, store 32B to each of Bhi/Blo row
#define CVTS(v, r) do {                                                        \
    uint32_t hp_[8], lp_[8];                                                   \
    _Pragma("unroll") for (int q_ = 0; q_ < 8; q_++) {                         \
        float a0_ = (v)[2 * q_], a1_ = (v)[2 * q_ + 1];                        \
        hp_[q_] = pack_bf16x2(a0_, a1_);                                       \
        float r0_ = a0_ - __uint_as_float(hp_[q_] << 16);                      \
        float r1_ = a1_ - __uint_as_float(hp_[q_] & 0xFFFF0000u);              \
        lp_[q_] = pack_bf16x2(r0_, r1_);                                       \
    }                                                                          \
    char* d_ = smem + BHI_OFF + tid * 144 + (r) * 32;                          \
    *(uint4*)d_        = make_uint4(hp_[0], hp_[1], hp_[2], hp_[3]);           \
    *(uint4*)(d_ + 16) = make_uint4(hp_[4], hp_[5], hp_[6], hp_[7]);           \
    char* e_ = d_ + (BLO_OFF - BHI_OFF);                                       \
    *(uint4*)e_        = make_uint4(lp_[0], lp_[1], lp_[2], lp_[3]);           \
    *(uint4*)(e_ + 16) = make_uint4(lp_[4], lp_[5], lp_[6], lp_[7]);           \
} while (0)

__global__ __launch_bounds__(THREADS, 2) void sconv_hmma_kernel(
    const float* __restrict__ input,
    const float* __restrict__ bias,
    const int*   __restrict__ selh,
    const int*   __restrict__ selw,
    float*       __restrict__ out)
{
    extern __shared__ char smem[];

    const int tid  = threadIdx.x;
    const int lane = tid & 31;
    const int w    = tid >> 5;
    const int fq   = lane & 3;
    const int fr   = lane >> 2;

    const int y   = blockIdx.x >> 2;
    const int px0 = (blockIdx.x & 3) * 16;

    // ---- gather mapping: thread owns B row tid = b*16 + pxl, 64 c per chunk ----
    const int b   = tid >> 4;
    const int pxl = tid & 15;
    const int pxc = min(px0 + pxl, Y_DIM - 1);
    const int sh  = selh[y * Y_DIM + pxc];
    const int sw  = selw[y * Y_DIM + pxc];
    const float* pbase = input + (b << 20) + (2 * y + sh) * 128 + 2 * pxc + sw;

    float acc[4][4][4];
#pragma unroll
    for (int i = 0; i < 4; i++)
#pragma unroll
        for (int j = 0; j < 4; j++)
#pragma unroll
            for (int q = 0; q < 4; q++) acc[i][j][q] = 0.f;

    for (int ch = 0; ch < 9; ch++) {
        __syncthreads();

        // ---- A slab prefetch into regs (L2-hot), stored after B LDGs issue ----
        uint4 aa[4];
#pragma unroll
        for (int i = 0; i < 4; i++) {
            int e    = tid + i * THREADS;       // 0..1023 over hi|lo
            int bsel = e >> 9;
            int e2   = e & 511;
            int m    = e2 >> 3;
            int q    = e2 & 7;
            aa[i] = *(const uint4*)((const char*)(bsel ? g_Alo : g_Ahi)
                                    + m * (KTOT * 2) + ch * 128 + q * 16);
        }

        // ---- B gather: 4 rounds of 16, 2-round pipelined (high MLP) ----
        const float* p = pbase + (ch / 3) * 128 + (ch - (ch / 3) * 3);
        {
            float v0[16], v1[16];
            LDGV(v0, 0);
            LDGV(v1, 1);
            CVTS(v0, 0);
            LDGV(v0, 2);
            CVTS(v1, 1);
            LDGV(v1, 3);
            // A store (aa long since landed)
#pragma unroll
            for (int i = 0; i < 4; i++) {
                int e    = tid + i * THREADS;
                int bsel = e >> 9;
                int e2   = e & 511;
                int m    = e2 >> 3;
                int q    = e2 & 7;
                *(uint4*)(smem + (bsel ? ALO_OFF : AHI_OFF) + m * 144 + q * 16) = aa[i];
            }
            CVTS(v0, 2);
            CVTS(v1, 3);
        }
        __syncthreads();

        // ---- compute: 4 k16 steps (R5 engine, 144B rows, conflict-free) ----
#pragma unroll
        for (int kq = 0; kq < 4; kq++) {
            uint32_t bh[4][2], bl[4][2];
#pragma unroll
            for (int nf = 0; nf < 4; nf++) {
                const char* pb = smem + BHI_OFF
                               + (w * 32 + nf * 8 + fr) * 144 + kq * 32 + fq * 4;
                bh[nf][0] = *(const uint32_t*)pb;
                bh[nf][1] = *(const uint32_t*)(pb + 16);
                bl[nf][0] = *(const uint32_t*)(pb + (BLO_OFF - BHI_OFF));
                bl[nf][1] = *(const uint32_t*)(pb + (BLO_OFF - BHI_OFF) + 16);
            }
#pragma unroll
            for (int mf = 0; mf < 4; mf++) {
                const char* pa = smem + AHI_OFF + (mf * 16 + fr) * 144 + kq * 32 + fq * 4;
                uint32_t ah[4], al[4];
                ah[0] = *(const uint32_t*)pa;
                ah[1] = *(const uint32_t*)(pa + 8 * 144);
                ah[2] = *(const uint32_t*)(pa + 16);
                ah[3] = *(const uint32_t*)(pa + 8 * 144 + 16);
                al[0] = *(const uint32_t*)(pa + ALO_OFF);
                al[1] = *(const uint32_t*)(pa + ALO_OFF + 8 * 144);
                al[2] = *(const uint32_t*)(pa + ALO_OFF + 16);
                al[3] = *(const uint32_t*)(pa + ALO_OFF + 8 * 144 + 16);
#pragma unroll
                for (int nf = 0; nf < 4; nf++) {
                    MMA(acc[mf][nf], ah, bh[nf]);
                    MMA(acc[mf][nf], ah, bl[nf]);
                    MMA(acc[mf][nf], al, bh[nf]);
                }
            }
        }
    }

    // ---- epilogue: scalar stores (odd output strides) ----
    const int npx   = min(16, Y_DIM - px0);
    const int ybase = y * Y_DIM + px0;

#pragma unroll
    for (int mf = 0; mf < 4; mf++) {
        const int o = mf * 16 + fr;
        const float bo0 = __ldg(bias + o);
        const float bo8 = __ldg(bias + o + 8);
#pragma unroll
        for (int nf = 0; nf < 4; nf++) {
            int n    = w * 32 + nf * 8 + 2 * fq;
            int bcol = n >> 4;
            int pp   = n & 15;
            long base0 = ((long)(bcol * COUT + o)) * (Y_DIM * Y_DIM) + ybase + pp;
            long base8 = base0 + 8L * (Y_DIM * Y_DIM);
            if (pp < npx) {
                out[base0] = acc[mf][nf][0] + bo0;
                out[base8] = acc[mf][nf][2] + bo8;
            }
            if (pp + 1 < npx) {
                out[base0 + 1] = acc[mf][nf][1] + bo0;
                out[base8 + 1] = acc[mf][nf][3] + bo8;
            }
        }
    }
}

extern "C" void kernel_launch(void* const* d_in, const int* in_sizes, int n_in,
                              void* d_out, int out_size)
{
    const float* input  = (const float*)d_in[0];
    const float* weight = (const float*)d_in[1];
    const float* bias   = (const float*)d_in[2];
    const int*   selh   = (const int*)d_in[3];
    const int*   selw   = (const int*)d_in[4];
    float*       out    = (float*)d_out;

    cudaFuncSetAttribute(sconv_hmma_kernel,
                         cudaFuncAttributeMaxDynamicSharedMemorySize, SMEM_TOTAL);

    prep_A_kernel<<<(COUT * KTOT + 255) / 256, 256>>>(weight);
    sconv_hmma_kernel<<<Y_DIM * 4, THREADS, SMEM_TOTAL>>>(input, bias, selh, selw, out);
}